// round 11
// baseline (speedup 1.0000x reference)
#include <cuda_runtime.h>
#include <cuda_fp16.h>
#include <cstdint>

#define DIM   192
#define NTOK  64
#define NH    6
#define HD    32
#define QKV_N 576
#define SCALE 0.17677669529663689f   // 1/sqrt(32)

#define ROWB 384                       // bytes per smem row (192 halves, swizzled, no pad)
#define BUFB (NTOK * ROWB)             // 24576 bytes per buffer
#define SMEM_BYTES (3 * BUFB)          // sA(Q/Y), sK, sV = 73728 B -> 3 CTAs/SM

// ---- persistent pre-packed operands ----
// qkv weights as MMA B fragments: [72 nblk][6 kpair][32 lane] -> uint4 {b0,b1 of kk, b0,b1 of kk+16}
__device__ uint4 g_qkv_wf[72 * 6 * 32];
// proj weights: [24 nblk][6 kpair][32 lane]
__device__ uint4 g_proj_wf[24 * 6 * 32];
// combined rpb+mask, fp16, fragment layout: [w][h][m][nt][lane] -> uint2
__device__ uint2 g_bias[64 * NH * 4 * 8 * 32];

#define QKV_FRAGS  (72 * 6 * 32)
#define PROJ_FRAGS (24 * 6 * 32)
#define BIAS_FRAGS (64 * NH * 4 * 8 * 32)
#define PREP_TOTAL (QKV_FRAGS + PROJ_FRAGS + BIAS_FRAGS)

__device__ __forceinline__ unsigned packh2(float a, float b) {
    __half2 h = __floats2half2_rn(a, b);
    return *(unsigned*)&h;
}

__global__ void prep_kernel(const float* __restrict__ qkv_w,
                            const float* __restrict__ proj_w,
                            const float* __restrict__ bias_table,
                            const int*   __restrict__ rel_idx,
                            const float* __restrict__ mask) {
    int i = blockIdx.x * blockDim.x + threadIdx.x;
    if (i < QKV_FRAGS) {
        int lane = i & 31, kp = (i >> 5) % 6, nblk = (i >> 5) / 6;
        int n = nblk * 8 + (lane >> 2);
        const float* wp = qkv_w + n * DIM + kp * 32 + (lane & 3) * 2;
        uint4 r;
        r.x = packh2(wp[0],  wp[1]);
        r.y = packh2(wp[8],  wp[9]);
        r.z = packh2(wp[16], wp[17]);
        r.w = packh2(wp[24], wp[25]);
        g_qkv_wf[i] = r;
        return;
    }
    int j = i - QKV_FRAGS;
    if (j < PROJ_FRAGS) {
        int lane = j & 31, kp = (j >> 5) % 6, nblk = (j >> 5) / 6;
        int n = nblk * 8 + (lane >> 2);
        const float* wp = proj_w + n * DIM + kp * 32 + (lane & 3) * 2;
        uint4 r;
        r.x = packh2(wp[0],  wp[1]);
        r.y = packh2(wp[8],  wp[9]);
        r.z = packh2(wp[16], wp[17]);
        r.w = packh2(wp[24], wp[25]);
        g_proj_wf[j] = r;
        return;
    }
    int t = j - PROJ_FRAGS;
    if (t < BIAS_FRAGS) {
        int lane = t & 31;
        int nt   = (t >> 5) & 7;
        int m    = (t >> 8) & 3;
        int rest = t >> 10;
        int h = rest % NH, w = rest / NH;
        int r0 = m * 16 + (lane >> 2);
        int c  = nt * 8 + (lane & 3) * 2;
        const float* mw = mask + (size_t)w * (NTOK * NTOK);
        float v00 = bias_table[rel_idx[r0 * 64 + c] * NH + h]           + mw[r0 * 64 + c];
        float v01 = bias_table[rel_idx[r0 * 64 + c + 1] * NH + h]       + mw[r0 * 64 + c + 1];
        float v10 = bias_table[rel_idx[(r0 + 8) * 64 + c] * NH + h]     + mw[(r0 + 8) * 64 + c];
        float v11 = bias_table[rel_idx[(r0 + 8) * 64 + c + 1] * NH + h] + mw[(r0 + 8) * 64 + c + 1];
        uint2 r;
        r.x = packh2(v00, v01);
        r.y = packh2(v10, v11);
        g_bias[t] = r;
    }
}

// ---- PTX helpers ----
__device__ __forceinline__ unsigned sptr(const void* p) {
    return (unsigned)__cvta_generic_to_shared(p);
}
// swizzled byte offset within a 64x192-half buffer: row r, column-byte cbyte (0..383)
__device__ __forceinline__ unsigned swz(int r, int cbyte) {
    return (unsigned)(r * ROWB + (cbyte ^ ((r & 7) << 4)));
}
__device__ __forceinline__ void ldm_x4(unsigned addr, unsigned& a0, unsigned& a1,
                                       unsigned& a2, unsigned& a3) {
    asm volatile("ldmatrix.sync.aligned.m8n8.x4.shared.b16 {%0,%1,%2,%3}, [%4];\n"
                 : "=r"(a0), "=r"(a1), "=r"(a2), "=r"(a3) : "r"(addr));
}
__device__ __forceinline__ void ldm_x4t(unsigned addr, unsigned& a0, unsigned& a1,
                                        unsigned& a2, unsigned& a3) {
    asm volatile("ldmatrix.sync.aligned.m8n8.x4.trans.shared.b16 {%0,%1,%2,%3}, [%4];\n"
                 : "=r"(a0), "=r"(a1), "=r"(a2), "=r"(a3) : "r"(addr));
}
__device__ __forceinline__ void mma16816(float c[4], unsigned a0, unsigned a1,
                                         unsigned a2, unsigned a3,
                                         unsigned b0, unsigned b1) {
    asm volatile(
        "mma.sync.aligned.m16n8k16.row.col.f32.f16.f16.f32 "
        "{%0,%1,%2,%3}, {%4,%5,%6,%7}, {%8,%9}, {%0,%1,%2,%3};\n"
        : "+f"(c[0]), "+f"(c[1]), "+f"(c[2]), "+f"(c[3])
        : "r"(a0), "r"(a1), "r"(a2), "r"(a3), "r"(b0), "r"(b1));
}

__global__ __launch_bounds__(256, 3)
void winattn_kernel(const float* __restrict__ x,
                    const float* __restrict__ qkv_b,
                    const float* __restrict__ proj_b,
                    float* __restrict__ out) {
    extern __shared__ __align__(16) char smem_raw[];
    char* sA = smem_raw;            // Q, then Y (head cols overwritten in stage 2)
    char* sK = smem_raw + BUFB;
    char* sV = smem_raw + 2 * BUFB;
    const unsigned uA = sptr(sA), uK = sptr(sK), uV = sptr(sV);

    const int b    = blockIdx.x;
    const int w    = b & 63;
    const int tid  = threadIdx.x;
    const int warp = tid >> 5;
    const int lane = tid & 31;

    const int warpM = warp & 3;       // 16-row group
    const int warpN = warp >> 2;      // 0..1: GEMM col half == head parity
    const int r0 = warpM * 16 + (lane >> 2);
    const int cq = (lane & 3) * 2;
    const int lrow = warpM * 16 + (lane & 15);      // ldmatrix row for this lane
    const int lcol8 = (lane >> 4) << 3;             // ldmatrix 8-col group select

    // ---------- stage 0: x A-fragments straight from gmem ----------
    unsigned Afr[12][4];
    {
        const float* xw = x + (size_t)b * (NTOK * DIM);
        const int ar = r0;
        #pragma unroll
        for (int kb = 0; kb < 12; kb++) {
            const int c = kb * 16 + cq;
            float2 v00 = *(const float2*)&xw[ar * DIM + c];
            float2 v10 = *(const float2*)&xw[(ar + 8) * DIM + c];
            float2 v01 = *(const float2*)&xw[ar * DIM + c + 8];
            float2 v11 = *(const float2*)&xw[(ar + 8) * DIM + c + 8];
            Afr[kb][0] = packh2(v00.x, v00.y);
            Afr[kb][1] = packh2(v10.x, v10.y);
            Afr[kb][2] = packh2(v01.x, v01.y);
            Afr[kb][3] = packh2(v11.x, v11.y);
        }
    }

    // ---------- stage 1: qkv = x @ W^T + b ----------
    #pragma unroll 1
    for (int nb = 0; nb < 9; nb++) {
        float acc[4][4] = {};
        #pragma unroll
        for (int kp = 0; kp < 6; kp++) {
            #pragma unroll
            for (int nt = 0; nt < 4; nt++) {
                uint4 bb = g_qkv_wf[((nb * 8 + warpN * 4 + nt) * 6 + kp) * 32 + lane];
                mma16816(acc[nt], Afr[2*kp][0], Afr[2*kp][1], Afr[2*kp][2], Afr[2*kp][3],
                         bb.x, bb.y);
                mma16816(acc[nt], Afr[2*kp+1][0], Afr[2*kp+1][1], Afr[2*kp+1][2], Afr[2*kp+1][3],
                         bb.z, bb.w);
            }
        }
        const unsigned ub = (nb < 3) ? uA : ((nb < 6) ? uK : uV);
        const int cb = (nb < 3) ? nb : ((nb < 6) ? nb - 3 : nb - 6);
        const float scl = (nb < 3) ? SCALE : 1.0f;
        #pragma unroll
        for (int nt = 0; nt < 4; nt++) {
            int cc = nb * 64 + warpN * 32 + nt * 8 + cq;
            int cl = cb * 64 + warpN * 32 + nt * 8 + cq;
            float bb0 = qkv_b[cc], bb1 = qkv_b[cc + 1];
            *(unsigned*)(smem_raw + (ub - uA) + swz(r0, cl * 2)) =
                packh2((acc[nt][0] + bb0) * scl, (acc[nt][1] + bb1) * scl);
            *(unsigned*)(smem_raw + (ub - uA) + swz(r0 + 8, cl * 2)) =
                packh2((acc[nt][2] + bb0) * scl, (acc[nt][3] + bb1) * scl);
        }
    }
    __syncthreads();

    // ---------- stage 2: attention; heads hi*2 + warpN; barrier-free loop ----------
    #pragma unroll 1
    for (int hi = 0; hi < 3; hi++) {
        const int h = hi * 2 + warpN;
        float sc[8][4] = {};
        #pragma unroll
        for (int kk2 = 0; kk2 < 2; kk2++) {
            unsigned qa0, qa1, qa2, qa3;
            ldm_x4(uA + swz(lrow, (h * HD + kk2 * 16 + lcol8) * 2), qa0, qa1, qa2, qa3);
            #pragma unroll
            for (int ntp = 0; ntp < 4; ntp++) {
                unsigned k0, k1, k2, k3;
                ldm_x4(uK + swz(ntp * 16 + (lane & 15), (h * HD + kk2 * 16 + lcol8) * 2),
                       k0, k1, k2, k3);
                mma16816(sc[2*ntp],   qa0, qa1, qa2, qa3, k0, k2);
                mma16816(sc[2*ntp+1], qa0, qa1, qa2, qa3, k1, k3);
            }
        }
        // + combined rpb+mask
        {
            const uint2* bp = &g_bias[(((w * NH + h) * 4 + warpM) * 8) * 32 + lane];
            #pragma unroll
            for (int nt = 0; nt < 8; nt++) {
                uint2 bv = bp[nt * 32];
                __half2 lo = *(__half2*)&bv.x, hi2 = *(__half2*)&bv.y;
                sc[nt][0] += __low2float(lo);  sc[nt][1] += __high2float(lo);
                sc[nt][2] += __low2float(hi2); sc[nt][3] += __high2float(hi2);
            }
        }
        // intra-warp softmax (rows r0, r0+8)
        float m0 = -1e30f, m1 = -1e30f;
        #pragma unroll
        for (int nt = 0; nt < 8; nt++) {
            m0 = fmaxf(m0, fmaxf(sc[nt][0], sc[nt][1]));
            m1 = fmaxf(m1, fmaxf(sc[nt][2], sc[nt][3]));
        }
        m0 = fmaxf(m0, __shfl_xor_sync(0xffffffffu, m0, 1));
        m0 = fmaxf(m0, __shfl_xor_sync(0xffffffffu, m0, 2));
        m1 = fmaxf(m1, __shfl_xor_sync(0xffffffffu, m1, 1));
        m1 = fmaxf(m1, __shfl_xor_sync(0xffffffffu, m1, 2));
        float s0 = 0.f, s1 = 0.f;
        #pragma unroll
        for (int nt = 0; nt < 8; nt++) {
            sc[nt][0] = __expf(sc[nt][0] - m0);
            sc[nt][1] = __expf(sc[nt][1] - m0);
            sc[nt][2] = __expf(sc[nt][2] - m1);
            sc[nt][3] = __expf(sc[nt][3] - m1);
            s0 += sc[nt][0] + sc[nt][1];
            s1 += sc[nt][2] + sc[nt][3];
        }
        s0 += __shfl_xor_sync(0xffffffffu, s0, 1);
        s0 += __shfl_xor_sync(0xffffffffu, s0, 2);
        s1 += __shfl_xor_sync(0xffffffffu, s1, 1);
        s1 += __shfl_xor_sync(0xffffffffu, s1, 2);
        const float inv0 = 1.0f / s0;
        const float inv1 = 1.0f / s1;

        // P @ V : P from score C-fragments in regs; V via ldm_x4 trans
        float o[4][4] = {};
        #pragma unroll
        for (int j = 0; j < 4; j++) {
            unsigned a0 = packh2(sc[2*j][0]   * inv0, sc[2*j][1]   * inv0);
            unsigned a1 = packh2(sc[2*j][2]   * inv1, sc[2*j][3]   * inv1);
            unsigned a2 = packh2(sc[2*j+1][0] * inv0, sc[2*j+1][1] * inv0);
            unsigned a3 = packh2(sc[2*j+1][2] * inv1, sc[2*j+1][3] * inv1);
            #pragma unroll
            for (int ntp = 0; ntp < 2; ntp++) {
                unsigned v0, v1, v2, v3;
                ldm_x4t(uV + swz(j * 16 + (lane & 15), (h * HD + ntp * 16 + lcol8) * 2),
                        v0, v1, v2, v3);
                mma16816(o[2*ntp],   a0, a1, a2, a3, v0, v1);
                mma16816(o[2*ntp+1], a0, a1, a2, a3, v2, v3);
            }
        }
        // Y over Q's head columns (own rows, own head-parity cols -> no cross-warp hazard)
        #pragma unroll
        for (int nt = 0; nt < 4; nt++) {
            int cc = h * HD + nt * 8 + cq;
            *(unsigned*)(sA + swz(r0,     cc * 2)) = packh2(o[nt][0], o[nt][1]);
            *(unsigned*)(sA + swz(r0 + 8, cc * 2)) = packh2(o[nt][2], o[nt][3]);
        }
    }
    __syncthreads();

    // ---------- stage 3: out = y @ proj_w^T + proj_b ----------
    {
        unsigned Yfr[12][4];
        #pragma unroll
        for (int kb = 0; kb < 12; kb++)
            ldm_x4(uA + swz(lrow, (kb * 16 + lcol8) * 2),
                   Yfr[kb][0], Yfr[kb][1], Yfr[kb][2], Yfr[kb][3]);

        float* og = out + (size_t)b * (NTOK * DIM);
        #pragma unroll 1
        for (int nb = 0; nb < 3; nb++) {
            float acc[4][4] = {};
            #pragma unroll
            for (int kp = 0; kp < 6; kp++) {
                #pragma unroll
                for (int nt = 0; nt < 4; nt++) {
                    uint4 bb = g_proj_wf[((nb * 8 + warpN * 4 + nt) * 6 + kp) * 32 + lane];
                    mma16816(acc[nt], Yfr[2*kp][0], Yfr[2*kp][1], Yfr[2*kp][2], Yfr[2*kp][3],
                             bb.x, bb.y);
                    mma16816(acc[nt], Yfr[2*kp+1][0], Yfr[2*kp+1][1], Yfr[2*kp+1][2], Yfr[2*kp+1][3],
                             bb.z, bb.w);
                }
            }
            #pragma unroll
            for (int nt = 0; nt < 4; nt++) {
                int cc = nb * 64 + warpN * 32 + nt * 8 + cq;
                float pb0 = proj_b[cc], pb1 = proj_b[cc + 1];
                *(float2*)&og[r0 * DIM + cc] =
                    make_float2(acc[nt][0] + pb0, acc[nt][1] + pb1);
                *(float2*)&og[(r0 + 8) * DIM + cc] =
                    make_float2(acc[nt][2] + pb0, acc[nt][3] + pb1);
            }
        }
    }
}

extern "C" void kernel_launch(void* const* d_in, const int* in_sizes, int n_in,
                              void* d_out, int out_size) {
    const float* x          = (const float*)d_in[0];
    const float* mask       = (const float*)d_in[1];
    const float* qkv_w      = (const float*)d_in[2];
    const float* qkv_b      = (const float*)d_in[3];
    const float* proj_w     = (const float*)d_in[4];
    const float* proj_b     = (const float*)d_in[5];
    const float* bias_table = (const float*)d_in[6];
    const int*   rel_idx    = (const int*)d_in[7];
    float* out = (float*)d_out;

    prep_kernel<<<(PREP_TOTAL + 255) / 256, 256>>>(qkv_w, proj_w, bias_table, rel_idx, mask);

    cudaFuncSetAttribute(winattn_kernel,
                         cudaFuncAttributeMaxDynamicSharedMemorySize, SMEM_BYTES);
    winattn_kernel<<<8192, 256, SMEM_BYTES>>>(x, qkv_b, proj_b, out);
}

// round 12
// speedup vs baseline: 1.2191x; 1.2191x over previous
#include <cuda_runtime.h>
#include <cuda_fp16.h>
#include <cstdint>

#define DIM   192
#define NTOK  64
#define NH    6
#define HD    32
#define QKV_N 576
#define SCALE 0.17677669529663689f   // 1/sqrt(32)
#define LOG2E 1.4426950408889634f

#define XS 200   // fp16 row stride (halves): 400B/row -> ldmatrix conflict-free

#define SMEM_BYTES (4 * NTOK * XS * 2)   // sX(unused alias), sQ/sY, sK, sV = 102400 B

// ---- persistent pre-packed operands ----
// qkv weights as MMA B fragments: [72 nblk][6 kpair][32 lane] -> uint4 {b0,b1 of kk, b0,b1 of kk+16}
__device__ uint4 g_qkv_wf[72 * 6 * 32];
// proj weights: [24 nblk][6 kpair][32 lane]
__device__ uint4 g_proj_wf[24 * 6 * 32];
// combined (rpb+mask)*log2e, fp16, fragment layout: [w][h][m][nt][lane] -> uint2
__device__ uint2 g_bias[64 * NH * 4 * 8 * 32];

#define QKV_FRAGS  (72 * 6 * 32)
#define PROJ_FRAGS (24 * 6 * 32)
#define BIAS_FRAGS (64 * NH * 4 * 8 * 32)
#define PREP_TOTAL (QKV_FRAGS + PROJ_FRAGS + BIAS_FRAGS)

__device__ __forceinline__ unsigned packh2(float a, float b) {
    __half2 h = __floats2half2_rn(a, b);
    return *(unsigned*)&h;
}
__device__ __forceinline__ float ex2(float x) {
    float r;
    asm("ex2.approx.f32 %0, %1;" : "=f"(r) : "f"(x));
    return r;
}

__global__ void prep_kernel(const float* __restrict__ qkv_w,
                            const float* __restrict__ proj_w,
                            const float* __restrict__ bias_table,
                            const int*   __restrict__ rel_idx,
                            const float* __restrict__ mask) {
    int i = blockIdx.x * blockDim.x + threadIdx.x;
    if (i < QKV_FRAGS) {
        int lane = i & 31, kp = (i >> 5) % 6, nblk = (i >> 5) / 6;
        int n = nblk * 8 + (lane >> 2);
        const float* wp = qkv_w + n * DIM + kp * 32 + (lane & 3) * 2;
        uint4 r;
        r.x = packh2(wp[0],  wp[1]);
        r.y = packh2(wp[8],  wp[9]);
        r.z = packh2(wp[16], wp[17]);
        r.w = packh2(wp[24], wp[25]);
        g_qkv_wf[i] = r;
        return;
    }
    int j = i - QKV_FRAGS;
    if (j < PROJ_FRAGS) {
        int lane = j & 31, kp = (j >> 5) % 6, nblk = (j >> 5) / 6;
        int n = nblk * 8 + (lane >> 2);
        const float* wp = proj_w + n * DIM + kp * 32 + (lane & 3) * 2;
        uint4 r;
        r.x = packh2(wp[0],  wp[1]);
        r.y = packh2(wp[8],  wp[9]);
        r.z = packh2(wp[16], wp[17]);
        r.w = packh2(wp[24], wp[25]);
        g_proj_wf[j] = r;
        return;
    }
    int t = j - PROJ_FRAGS;
    if (t < BIAS_FRAGS) {
        int lane = t & 31;
        int nt   = (t >> 5) & 7;
        int m    = (t >> 8) & 3;
        int rest = t >> 10;
        int h = rest % NH, w = rest / NH;
        int r0 = m * 16 + (lane >> 2);
        int c  = nt * 8 + (lane & 3) * 2;
        const float* mw = mask + (size_t)w * (NTOK * NTOK);
        float v00 = (bias_table[rel_idx[r0 * 64 + c] * NH + h]           + mw[r0 * 64 + c]) * LOG2E;
        float v01 = (bias_table[rel_idx[r0 * 64 + c + 1] * NH + h]       + mw[r0 * 64 + c + 1]) * LOG2E;
        float v10 = (bias_table[rel_idx[(r0 + 8) * 64 + c] * NH + h]     + mw[(r0 + 8) * 64 + c]) * LOG2E;
        float v11 = (bias_table[rel_idx[(r0 + 8) * 64 + c + 1] * NH + h] + mw[(r0 + 8) * 64 + c + 1]) * LOG2E;
        uint2 r;
        r.x = packh2(v00, v01);
        r.y = packh2(v10, v11);
        g_bias[t] = r;
    }
}

// ---- PTX helpers ----
__device__ __forceinline__ unsigned sptr(const void* p) {
    return (unsigned)__cvta_generic_to_shared(p);
}
__device__ __forceinline__ void ldm_x4(unsigned addr, unsigned& a0, unsigned& a1,
                                       unsigned& a2, unsigned& a3) {
    asm volatile("ldmatrix.sync.aligned.m8n8.x4.shared.b16 {%0,%1,%2,%3}, [%4];\n"
                 : "=r"(a0), "=r"(a1), "=r"(a2), "=r"(a3) : "r"(addr));
}
__device__ __forceinline__ void ldm_x4t(unsigned addr, unsigned& a0, unsigned& a1,
                                        unsigned& a2, unsigned& a3) {
    asm volatile("ldmatrix.sync.aligned.m8n8.x4.trans.shared.b16 {%0,%1,%2,%3}, [%4];\n"
                 : "=r"(a0), "=r"(a1), "=r"(a2), "=r"(a3) : "r"(addr));
}
__device__ __forceinline__ void mma16816(float c[4], unsigned a0, unsigned a1,
                                         unsigned a2, unsigned a3,
                                         unsigned b0, unsigned b1) {
    asm volatile(
        "mma.sync.aligned.m16n8k16.row.col.f32.f16.f16.f32 "
        "{%0,%1,%2,%3}, {%4,%5,%6,%7}, {%8,%9}, {%0,%1,%2,%3};\n"
        : "+f"(c[0]), "+f"(c[1]), "+f"(c[2]), "+f"(c[3])
        : "r"(a0), "r"(a1), "r"(a2), "r"(a3), "r"(b0), "r"(b1));
}

__global__ __launch_bounds__(256, 2)
void winattn_kernel(const float* __restrict__ x,
                    const float* __restrict__ qkv_b,
                    const float* __restrict__ proj_b,
                    float* __restrict__ out) {
    extern __shared__ __align__(16) char smem_raw[];
    __half* sQ = (__half*)smem_raw;            // Q, then Y head-by-head
    __half* sK = sQ + NTOK * XS;
    __half* sV = sK + NTOK * XS;

    const int b    = blockIdx.x;
    const int w    = b & 63;
    const int tid  = threadIdx.x;
    const int warp = tid >> 5;
    const int lane = tid & 31;

    const int warpM = warp & 3;       // 16-row group
    const int warpN = warp >> 2;      // 0..1: GEMM col half == head parity
    const int r0 = warpM * 16 + (lane >> 2);
    const int cq = (lane & 3) * 2;

    // ---------- stage 0: x A-fragments straight from gmem ----------
    unsigned Afr[12][4];
    {
        const float* xw = x + (size_t)b * (NTOK * DIM);
        const int ar = r0;
        #pragma unroll
        for (int kb = 0; kb < 12; kb++) {
            const int c = kb * 16 + cq;
            float2 v00 = *(const float2*)&xw[ar * DIM + c];
            float2 v10 = *(const float2*)&xw[(ar + 8) * DIM + c];
            float2 v01 = *(const float2*)&xw[ar * DIM + c + 8];
            float2 v11 = *(const float2*)&xw[(ar + 8) * DIM + c + 8];
            Afr[kb][0] = packh2(v00.x, v00.y);
            Afr[kb][1] = packh2(v10.x, v10.y);
            Afr[kb][2] = packh2(v01.x, v01.y);
            Afr[kb][3] = packh2(v11.x, v11.y);
        }
    }

    // ---------- stage 1: qkv = x @ W^T + b ----------
    const float QSCL = SCALE * LOG2E;   // fold softmax log2e into Q
    #pragma unroll 1
    for (int nb = 0; nb < 9; nb++) {
        float acc[4][4] = {};
        #pragma unroll
        for (int kp = 0; kp < 6; kp++) {
            #pragma unroll
            for (int nt = 0; nt < 4; nt++) {
                uint4 bb = g_qkv_wf[((nb * 8 + warpN * 4 + nt) * 6 + kp) * 32 + lane];
                mma16816(acc[nt], Afr[2*kp][0], Afr[2*kp][1], Afr[2*kp][2], Afr[2*kp][3],
                         bb.x, bb.y);
                mma16816(acc[nt], Afr[2*kp+1][0], Afr[2*kp+1][1], Afr[2*kp+1][2], Afr[2*kp+1][3],
                         bb.z, bb.w);
            }
        }
        __half* dstbuf = (nb < 3) ? sQ : ((nb < 6) ? sK : sV);
        const int cb = (nb < 3) ? nb : ((nb < 6) ? nb - 3 : nb - 6);
        const float scl = (nb < 3) ? QSCL : 1.0f;
        #pragma unroll
        for (int nt = 0; nt < 4; nt++) {
            int cc = nb * 64 + warpN * 32 + nt * 8 + cq;
            int cl = cb * 64 + warpN * 32 + nt * 8 + cq;
            float bb0 = qkv_b[cc], bb1 = qkv_b[cc + 1];
            *(__half2*)&dstbuf[r0 * XS + cl] =
                __floats2half2_rn((acc[nt][0] + bb0) * scl, (acc[nt][1] + bb1) * scl);
            *(__half2*)&dstbuf[(r0 + 8) * XS + cl] =
                __floats2half2_rn((acc[nt][2] + bb0) * scl, (acc[nt][3] + bb1) * scl);
        }
    }
    __syncthreads();

    // ---------- stage 2: attention; head order staggered by warpM ----------
    // scores (after Q prescale + bias) are already in log2 domain -> ex2 directly.
    // No max subtraction: scores are O(1) here, exact softmax unchanged.
    #pragma unroll 1
    for (int hi = 0; hi < 3; hi++) {
        const int hh = (hi + warpM) % 3;       // stagger softmax bursts across SMSP warps
        const int h = hh * 2 + warpN;
        float sc[8][4] = {};
        #pragma unroll
        for (int kk2 = 0; kk2 < 2; kk2++) {
            unsigned qa0, qa1, qa2, qa3;
            ldm_x4(sptr(&sQ[(warpM * 16 + (lane & 15)) * XS + h * HD + kk2 * 16 + ((lane >> 4) << 3)]),
                   qa0, qa1, qa2, qa3);
            #pragma unroll
            for (int ntp = 0; ntp < 4; ntp++) {
                unsigned k0, k1, k2, k3;
                ldm_x4(sptr(&sK[(ntp * 16 + (lane & 15)) * XS + h * HD + kk2 * 16 +
                               ((lane >> 4) << 3)]),
                       k0, k1, k2, k3);
                mma16816(sc[2*ntp],   qa0, qa1, qa2, qa3, k0, k2);
                mma16816(sc[2*ntp+1], qa0, qa1, qa2, qa3, k1, k3);
            }
        }
        // + combined (rpb+mask)*log2e
        {
            const uint2* bp = &g_bias[(((w * NH + h) * 4 + warpM) * 8) * 32 + lane];
            #pragma unroll
            for (int nt = 0; nt < 8; nt++) {
                uint2 bv = bp[nt * 32];
                __half2 lo = *(__half2*)&bv.x, hi2 = *(__half2*)&bv.y;
                sc[nt][0] += __low2float(lo);  sc[nt][1] += __high2float(lo);
                sc[nt][2] += __low2float(hi2); sc[nt][3] += __high2float(hi2);
            }
        }
        // softmax without max-sub: exp2 then sum
        float s0 = 0.f, s1 = 0.f;
        #pragma unroll
        for (int nt = 0; nt < 8; nt++) {
            sc[nt][0] = ex2(sc[nt][0]);
            sc[nt][1] = ex2(sc[nt][1]);
            sc[nt][2] = ex2(sc[nt][2]);
            sc[nt][3] = ex2(sc[nt][3]);
            s0 += sc[nt][0] + sc[nt][1];
            s1 += sc[nt][2] + sc[nt][3];
        }
        s0 += __shfl_xor_sync(0xffffffffu, s0, 1);
        s0 += __shfl_xor_sync(0xffffffffu, s0, 2);
        s1 += __shfl_xor_sync(0xffffffffu, s1, 1);
        s1 += __shfl_xor_sync(0xffffffffu, s1, 2);
        const float inv0 = 1.0f / s0;
        const float inv1 = 1.0f / s1;

        // P @ V : P fragments built in-register from score C-fragments
        float o[4][4] = {};
        #pragma unroll
        for (int j = 0; j < 4; j++) {
            unsigned a0 = packh2(sc[2*j][0]   * inv0, sc[2*j][1]   * inv0);
            unsigned a1 = packh2(sc[2*j][2]   * inv1, sc[2*j][3]   * inv1);
            unsigned a2 = packh2(sc[2*j+1][0] * inv0, sc[2*j+1][1] * inv0);
            unsigned a3 = packh2(sc[2*j+1][2] * inv1, sc[2*j+1][3] * inv1);
            #pragma unroll
            for (int ntp = 0; ntp < 2; ntp++) {
                unsigned v0, v1, v2, v3;
                ldm_x4t(sptr(&sV[(j * 16 + (lane & 15)) * XS + h * HD + ntp * 16 +
                                ((lane >> 4) << 3)]),
                        v0, v1, v2, v3);
                mma16816(o[2*ntp],   a0, a1, a2, a3, v0, v1);
                mma16816(o[2*ntp+1], a0, a1, a2, a3, v2, v3);
            }
        }
        // Y over Q's head columns (own rows, own head-parity cols -> no cross-warp hazard)
        #pragma unroll
        for (int nt = 0; nt < 4; nt++) {
            int cc = h * HD + nt * 8 + cq;
            *(__half2*)&sQ[r0 * XS + cc]       = __floats2half2_rn(o[nt][0], o[nt][1]);
            *(__half2*)&sQ[(r0 + 8) * XS + cc] = __floats2half2_rn(o[nt][2], o[nt][3]);
        }
    }
    __syncthreads();

    // ---------- stage 3: out = y @ proj_w^T + proj_b ----------
    {
        unsigned Yfr[12][4];
        unsigned ybase = sptr(&sQ[(warpM * 16 + (lane & 15)) * XS + ((lane >> 4) << 3)]);
        #pragma unroll
        for (int kb = 0; kb < 12; kb++)
            ldm_x4(ybase + kb * 32, Yfr[kb][0], Yfr[kb][1], Yfr[kb][2], Yfr[kb][3]);

        float* og = out + (size_t)b * (NTOK * DIM);
        #pragma unroll 1
        for (int nb = 0; nb < 3; nb++) {
            float acc[4][4] = {};
            #pragma unroll
            for (int kp = 0; kp < 6; kp++) {
                #pragma unroll
                for (int nt = 0; nt < 4; nt++) {
                    uint4 bb = g_proj_wf[((nb * 8 + warpN * 4 + nt) * 6 + kp) * 32 + lane];
                    mma16816(acc[nt], Yfr[2*kp][0], Yfr[2*kp][1], Yfr[2*kp][2], Yfr[2*kp][3],
                             bb.x, bb.y);
                    mma16816(acc[nt], Yfr[2*kp+1][0], Yfr[2*kp+1][1], Yfr[2*kp+1][2], Yfr[2*kp+1][3],
                             bb.z, bb.w);
                }
            }
            #pragma unroll
            for (int nt = 0; nt < 4; nt++) {
                int cc = nb * 64 + warpN * 32 + nt * 8 + cq;
                float pb0 = proj_b[cc], pb1 = proj_b[cc + 1];
                *(float2*)&og[r0 * DIM + cc] =
                    make_float2(acc[nt][0] + pb0, acc[nt][1] + pb1);
                *(float2*)&og[(r0 + 8) * DIM + cc] =
                    make_float2(acc[nt][2] + pb0, acc[nt][3] + pb1);
            }
        }
    }
}

extern "C" void kernel_launch(void* const* d_in, const int* in_sizes, int n_in,
                              void* d_out, int out_size) {
    const float* x          = (const float*)d_in[0];
    const float* mask       = (const float*)d_in[1];
    const float* qkv_w      = (const float*)d_in[2];
    const float* qkv_b      = (const float*)d_in[3];
    const float* proj_w     = (const float*)d_in[4];
    const float* proj_b     = (const float*)d_in[5];
    const float* bias_table = (const float*)d_in[6];
    const int*   rel_idx    = (const int*)d_in[7];
    float* out = (float*)d_out;

    prep_kernel<<<(PREP_TOTAL + 255) / 256, 256>>>(qkv_w, proj_w, bias_table, rel_idx, mask);

    cudaFuncSetAttribute(winattn_kernel,
                         cudaFuncAttributeMaxDynamicSharedMemorySize, SMEM_BYTES);
    winattn_kernel<<<8192, 256, SMEM_BYTES>>>(x, qkv_b, proj_b, out);
}

// round 13
// speedup vs baseline: 1.3467x; 1.1046x over previous
#include <cuda_runtime.h>
#include <cuda_fp16.h>
#include <cstdint>

#define DIM   192
#define NTOK  64
#define NH    6
#define HD    32
#define QKV_N 576
#define SCALE 0.17677669529663689f   // 1/sqrt(32)
#define LOG2E 1.4426950408889634f
#define QSCL  (SCALE * LOG2E)

#define XS 200   // fp16 row stride (halves): 400B/row -> ldmatrix conflict-free

#define SMEM_BYTES (3 * NTOK * XS * 2)   // sQ(/sY), sK, sV = 76800 B -> L1D carveout ~74KB

// ---- persistent pre-packed operands ----
// qkv weights as MMA B fragments: [72 nblk][6 kpair][32 lane] -> uint4 {b0,b1 of kk, b0,b1 of kk+16}
// Q-section (n<192) pre-scaled by SCALE*log2e.
__device__ uint4 g_qkv_wf[72 * 6 * 32];
// proj weights: [24 nblk][6 kpair][32 lane]
__device__ uint4 g_proj_wf[24 * 6 * 32];
// combined (rpb+mask)*log2e, fp16, fragment layout: [w][h][m][nt][lane] -> uint2
__device__ uint2 g_bias[64 * NH * 4 * 8 * 32];
// qkv bias, Q-section pre-scaled
__device__ float g_qkvb[QKV_N];

#define QKV_FRAGS  (72 * 6 * 32)
#define PROJ_FRAGS (24 * 6 * 32)
#define BIAS_FRAGS (64 * NH * 4 * 8 * 32)
#define PREP_TOTAL (QKV_FRAGS + PROJ_FRAGS + BIAS_FRAGS + QKV_N)

__device__ __forceinline__ unsigned packh2(float a, float b) {
    __half2 h = __floats2half2_rn(a, b);
    return *(unsigned*)&h;
}
__device__ __forceinline__ float ex2(float x) {
    float r;
    asm("ex2.approx.f32 %0, %1;" : "=f"(r) : "f"(x));
    return r;
}

__global__ void prep_kernel(const float* __restrict__ qkv_w,
                            const float* __restrict__ proj_w,
                            const float* __restrict__ bias_table,
                            const int*   __restrict__ rel_idx,
                            const float* __restrict__ mask,
                            const float* __restrict__ qkv_b) {
    int i = blockIdx.x * blockDim.x + threadIdx.x;
    if (i < QKV_FRAGS) {
        int lane = i & 31, kp = (i >> 5) % 6, nblk = (i >> 5) / 6;
        int n = nblk * 8 + (lane >> 2);
        float s = (n < 192) ? QSCL : 1.0f;    // fold softmax scale into Q weights
        const float* wp = qkv_w + n * DIM + kp * 32 + (lane & 3) * 2;
        uint4 r;
        r.x = packh2(wp[0]  * s, wp[1]  * s);
        r.y = packh2(wp[8]  * s, wp[9]  * s);
        r.z = packh2(wp[16] * s, wp[17] * s);
        r.w = packh2(wp[24] * s, wp[25] * s);
        g_qkv_wf[i] = r;
        return;
    }
    int j = i - QKV_FRAGS;
    if (j < PROJ_FRAGS) {
        int lane = j & 31, kp = (j >> 5) % 6, nblk = (j >> 5) / 6;
        int n = nblk * 8 + (lane >> 2);
        const float* wp = proj_w + n * DIM + kp * 32 + (lane & 3) * 2;
        uint4 r;
        r.x = packh2(wp[0],  wp[1]);
        r.y = packh2(wp[8],  wp[9]);
        r.z = packh2(wp[16], wp[17]);
        r.w = packh2(wp[24], wp[25]);
        g_proj_wf[j] = r;
        return;
    }
    int t = j - PROJ_FRAGS;
    if (t < BIAS_FRAGS) {
        int lane = t & 31;
        int nt   = (t >> 5) & 7;
        int m    = (t >> 8) & 3;
        int rest = t >> 10;
        int h = rest % NH, w = rest / NH;
        int r0 = m * 16 + (lane >> 2);
        int c  = nt * 8 + (lane & 3) * 2;
        const float* mw = mask + (size_t)w * (NTOK * NTOK);
        float v00 = (bias_table[rel_idx[r0 * 64 + c] * NH + h]           + mw[r0 * 64 + c]) * LOG2E;
        float v01 = (bias_table[rel_idx[r0 * 64 + c + 1] * NH + h]       + mw[r0 * 64 + c + 1]) * LOG2E;
        float v10 = (bias_table[rel_idx[(r0 + 8) * 64 + c] * NH + h]     + mw[(r0 + 8) * 64 + c]) * LOG2E;
        float v11 = (bias_table[rel_idx[(r0 + 8) * 64 + c + 1] * NH + h] + mw[(r0 + 8) * 64 + c + 1]) * LOG2E;
        uint2 r;
        r.x = packh2(v00, v01);
        r.y = packh2(v10, v11);
        g_bias[t] = r;
        return;
    }
    int q = t - BIAS_FRAGS;
    if (q < QKV_N)
        g_qkvb[q] = qkv_b[q] * ((q < 192) ? QSCL : 1.0f);
}

// ---- PTX helpers ----
__device__ __forceinline__ unsigned sptr(const void* p) {
    return (unsigned)__cvta_generic_to_shared(p);
}
__device__ __forceinline__ void ldm_x4(unsigned addr, unsigned& a0, unsigned& a1,
                                       unsigned& a2, unsigned& a3) {
    asm volatile("ldmatrix.sync.aligned.m8n8.x4.shared.b16 {%0,%1,%2,%3}, [%4];\n"
                 : "=r"(a0), "=r"(a1), "=r"(a2), "=r"(a3) : "r"(addr));
}
__device__ __forceinline__ void ldm_x4t(unsigned addr, unsigned& a0, unsigned& a1,
                                        unsigned& a2, unsigned& a3) {
    asm volatile("ldmatrix.sync.aligned.m8n8.x4.trans.shared.b16 {%0,%1,%2,%3}, [%4];\n"
                 : "=r"(a0), "=r"(a1), "=r"(a2), "=r"(a3) : "r"(addr));
}
__device__ __forceinline__ void mma16816(float c[4], unsigned a0, unsigned a1,
                                         unsigned a2, unsigned a3,
                                         unsigned b0, unsigned b1) {
    asm volatile(
        "mma.sync.aligned.m16n8k16.row.col.f32.f16.f16.f32 "
        "{%0,%1,%2,%3}, {%4,%5,%6,%7}, {%8,%9}, {%0,%1,%2,%3};\n"
        : "+f"(c[0]), "+f"(c[1]), "+f"(c[2]), "+f"(c[3])
        : "r"(a0), "r"(a1), "r"(a2), "r"(a3), "r"(b0), "r"(b1));
}

__global__ __launch_bounds__(256, 2)
void winattn_kernel(const float* __restrict__ x,
                    const float* __restrict__ proj_b,
                    float* __restrict__ out) {
    extern __shared__ __align__(16) char smem_raw[];
    __half* sQ = (__half*)smem_raw;            // Q, then Y head-by-head
    __half* sK = sQ + NTOK * XS;
    __half* sV = sK + NTOK * XS;

    const int b    = blockIdx.x;
    const int w    = b & 63;
    const int tid  = threadIdx.x;
    const int warp = tid >> 5;
    const int lane = tid & 31;

    const int warpM = warp & 3;       // 16-row group
    const int warpN = warp >> 2;      // 0..1: GEMM col half == head parity
    const int r0 = warpM * 16 + (lane >> 2);
    const int cq = (lane & 3) * 2;

    // ---------- stage 0: x A-fragments straight from gmem ----------
    unsigned Afr[12][4];
    {
        const float* xw = x + (size_t)b * (NTOK * DIM);
        const int ar = r0;
        #pragma unroll
        for (int kb = 0; kb < 12; kb++) {
            const int c = kb * 16 + cq;
            float2 v00 = *(const float2*)&xw[ar * DIM + c];
            float2 v10 = *(const float2*)&xw[(ar + 8) * DIM + c];
            float2 v01 = *(const float2*)&xw[ar * DIM + c + 8];
            float2 v11 = *(const float2*)&xw[(ar + 8) * DIM + c + 8];
            Afr[kb][0] = packh2(v00.x, v00.y);
            Afr[kb][1] = packh2(v10.x, v10.y);
            Afr[kb][2] = packh2(v01.x, v01.y);
            Afr[kb][3] = packh2(v11.x, v11.y);
        }
    }

    // ---------- stage 1: qkv = x @ W^T + b (bias pre-loaded into C) ----------
    #pragma unroll 1
    for (int nb = 0; nb < 9; nb++) {
        float acc[4][4];
        #pragma unroll
        for (int nt = 0; nt < 4; nt++) {        // C init = bias (issues LDGs before MMAs)
            float2 bb = *(const float2*)&g_qkvb[nb * 64 + warpN * 32 + nt * 8 + cq];
            acc[nt][0] = bb.x; acc[nt][1] = bb.y;
            acc[nt][2] = bb.x; acc[nt][3] = bb.y;
        }
        #pragma unroll
        for (int kp = 0; kp < 6; kp++) {
            #pragma unroll
            for (int nt = 0; nt < 4; nt++) {
                uint4 bb = g_qkv_wf[((nb * 8 + warpN * 4 + nt) * 6 + kp) * 32 + lane];
                mma16816(acc[nt], Afr[2*kp][0], Afr[2*kp][1], Afr[2*kp][2], Afr[2*kp][3],
                         bb.x, bb.y);
                mma16816(acc[nt], Afr[2*kp+1][0], Afr[2*kp+1][1], Afr[2*kp+1][2], Afr[2*kp+1][3],
                         bb.z, bb.w);
            }
        }
        __half* dstbuf = (nb < 3) ? sQ : ((nb < 6) ? sK : sV);
        const int cb = (nb < 3) ? nb : ((nb < 6) ? nb - 3 : nb - 6);
        #pragma unroll
        for (int nt = 0; nt < 4; nt++) {
            int cl = cb * 64 + warpN * 32 + nt * 8 + cq;
            *(__half2*)&dstbuf[r0 * XS + cl]       = __floats2half2_rn(acc[nt][0], acc[nt][1]);
            *(__half2*)&dstbuf[(r0 + 8) * XS + cl] = __floats2half2_rn(acc[nt][2], acc[nt][3]);
        }
    }
    __syncthreads();

    // ---------- stage 2: attention; head order staggered by warpM ----------
    // Q pre-scaled by SCALE*log2e; bias table pre-scaled by log2e; C-init with bias.
    // Scores land in log2 domain -> ex2 directly, no max-sub (scores O(1), exact).
    #pragma unroll 1
    for (int hi = 0; hi < 3; hi++) {
        const int hh = (hi + warpM) % 3;       // stagger softmax bursts across SMSP warps
        const int h = hh * 2 + warpN;
        float sc[8][4];
        {   // C init = (rpb+mask)*log2e  (LDGs issued before the MMA burst)
            const uint2* bp = &g_bias[(((w * NH + h) * 4 + warpM) * 8) * 32 + lane];
            #pragma unroll
            for (int nt = 0; nt < 8; nt++) {
                uint2 bv = bp[nt * 32];
                __half2 lo = *(__half2*)&bv.x, hi2 = *(__half2*)&bv.y;
                sc[nt][0] = __low2float(lo);  sc[nt][1] = __high2float(lo);
                sc[nt][2] = __low2float(hi2); sc[nt][3] = __high2float(hi2);
            }
        }
        #pragma unroll
        for (int kk2 = 0; kk2 < 2; kk2++) {
            unsigned qa0, qa1, qa2, qa3;
            ldm_x4(sptr(&sQ[(warpM * 16 + (lane & 15)) * XS + h * HD + kk2 * 16 + ((lane >> 4) << 3)]),
                   qa0, qa1, qa2, qa3);
            #pragma unroll
            for (int ntp = 0; ntp < 4; ntp++) {
                unsigned k0, k1, k2, k3;
                ldm_x4(sptr(&sK[(ntp * 16 + (lane & 15)) * XS + h * HD + kk2 * 16 +
                               ((lane >> 4) << 3)]),
                       k0, k1, k2, k3);
                mma16816(sc[2*ntp],   qa0, qa1, qa2, qa3, k0, k2);
                mma16816(sc[2*ntp+1], qa0, qa1, qa2, qa3, k1, k3);
            }
        }
        // softmax: exp2 then sum (no max-sub)
        float s0 = 0.f, s1 = 0.f;
        #pragma unroll
        for (int nt = 0; nt < 8; nt++) {
            sc[nt][0] = ex2(sc[nt][0]);
            sc[nt][1] = ex2(sc[nt][1]);
            sc[nt][2] = ex2(sc[nt][2]);
            sc[nt][3] = ex2(sc[nt][3]);
            s0 += sc[nt][0] + sc[nt][1];
            s1 += sc[nt][2] + sc[nt][3];
        }
        s0 += __shfl_xor_sync(0xffffffffu, s0, 1);
        s0 += __shfl_xor_sync(0xffffffffu, s0, 2);
        s1 += __shfl_xor_sync(0xffffffffu, s1, 1);
        s1 += __shfl_xor_sync(0xffffffffu, s1, 2);
        const float inv0 = 1.0f / s0;
        const float inv1 = 1.0f / s1;

        // P @ V : P fragments built in-register from score C-fragments
        float o[4][4] = {};
        #pragma unroll
        for (int j = 0; j < 4; j++) {
            unsigned a0 = packh2(sc[2*j][0]   * inv0, sc[2*j][1]   * inv0);
            unsigned a1 = packh2(sc[2*j][2]   * inv1, sc[2*j][3]   * inv1);
            unsigned a2 = packh2(sc[2*j+1][0] * inv0, sc[2*j+1][1] * inv0);
            unsigned a3 = packh2(sc[2*j+1][2] * inv1, sc[2*j+1][3] * inv1);
            #pragma unroll
            for (int ntp = 0; ntp < 2; ntp++) {
                unsigned v0, v1, v2, v3;
                ldm_x4t(sptr(&sV[(j * 16 + (lane & 15)) * XS + h * HD + ntp * 16 +
                                ((lane >> 4) << 3)]),
                        v0, v1, v2, v3);
                mma16816(o[2*ntp],   a0, a1, a2, a3, v0, v1);
                mma16816(o[2*ntp+1], a0, a1, a2, a3, v2, v3);
            }
        }
        // Y over Q's head columns (own rows, own head-parity cols -> no cross-warp hazard)
        #pragma unroll
        for (int nt = 0; nt < 4; nt++) {
            int cc = h * HD + nt * 8 + cq;
            *(__half2*)&sQ[r0 * XS + cc]       = __floats2half2_rn(o[nt][0], o[nt][1]);
            *(__half2*)&sQ[(r0 + 8) * XS + cc] = __floats2half2_rn(o[nt][2], o[nt][3]);
        }
    }
    __syncthreads();

    // ---------- stage 3: out = y @ proj_w^T + proj_b (bias pre-loaded into C) ----------
    {
        unsigned Yfr[12][4];
        unsigned ybase = sptr(&sQ[(warpM * 16 + (lane & 15)) * XS + ((lane >> 4) << 3)]);
        #pragma unroll
        for (int kb = 0; kb < 12; kb++)
            ldm_x4(ybase + kb * 32, Yfr[kb][0], Yfr[kb][1], Yfr[kb][2], Yfr[kb][3]);

        float* og = out + (size_t)b * (NTOK * DIM);
        #pragma unroll 1
        for (int nb = 0; nb < 3; nb++) {
            float acc[4][4];
            #pragma unroll
            for (int nt = 0; nt < 4; nt++) {
                float2 pb = *(const float2*)&proj_b[nb * 64 + warpN * 32 + nt * 8 + cq];
                acc[nt][0] = pb.x; acc[nt][1] = pb.y;
                acc[nt][2] = pb.x; acc[nt][3] = pb.y;
            }
            #pragma unroll
            for (int kp = 0; kp < 6; kp++) {
                #pragma unroll
                for (int nt = 0; nt < 4; nt++) {
                    uint4 bb = g_proj_wf[((nb * 8 + warpN * 4 + nt) * 6 + kp) * 32 + lane];
                    mma16816(acc[nt], Yfr[2*kp][0], Yfr[2*kp][1], Yfr[2*kp][2], Yfr[2*kp][3],
                             bb.x, bb.y);
                    mma16816(acc[nt], Yfr[2*kp+1][0], Yfr[2*kp+1][1], Yfr[2*kp+1][2], Yfr[2*kp+1][3],
                             bb.z, bb.w);
                }
            }
            #pragma unroll
            for (int nt = 0; nt < 4; nt++) {
                int cc = nb * 64 + warpN * 32 + nt * 8 + cq;
                *(float2*)&og[r0 * DIM + cc]       = make_float2(acc[nt][0], acc[nt][1]);
                *(float2*)&og[(r0 + 8) * DIM + cc] = make_float2(acc[nt][2], acc[nt][3]);
            }
        }
    }
}

extern "C" void kernel_launch(void* const* d_in, const int* in_sizes, int n_in,
                              void* d_out, int out_size) {
    const float* x          = (const float*)d_in[0];
    const float* mask       = (const float*)d_in[1];
    const float* qkv_w      = (const float*)d_in[2];
    const float* qkv_b      = (const float*)d_in[3];
    const float* proj_w     = (const float*)d_in[4];
    const float* proj_b     = (const float*)d_in[5];
    const float* bias_table = (const float*)d_in[6];
    const int*   rel_idx    = (const int*)d_in[7];
    float* out = (float*)d_out;

    prep_kernel<<<(PREP_TOTAL + 255) / 256, 256>>>(qkv_w, proj_w, bias_table, rel_idx, mask, qkv_b);

    cudaFuncSetAttribute(winattn_kernel,
                         cudaFuncAttributeMaxDynamicSharedMemorySize, SMEM_BYTES);
    winattn_kernel<<<8192, 256, SMEM_BYTES>>>(x, proj_b, out);
}